// round 14
// baseline (speedup 1.0000x reference)
#include <cuda_runtime.h>
#include <cuda_fp16.h>
#include <cstdint>

#define N_NODES 50000
#define N_EDGES 600000
#define D 128

// ---------------- scratch (static device globals; no allocation) ----------
__device__ float  g_dis[N_NODES];
__device__ int    g_counts[N_NODES + 1];         // [N_NODES] = running total
__device__ int    g_base[N_NODES];
__device__ int    g_rank[N_EDGES];               // within-dst rank per edge
__device__ int    g_csr_src[N_EDGES];
__device__ __half g_wt[2][D * D];                // W^T fp16 per layer
__device__ __half g_hw[(size_t)N_NODES * D];     // hw' (dis-scaled) fp16
__device__ __half g_acth[(size_t)N_NODES * D];   // activation fp16
__device__ float  g_hw3[N_NODES];

// ---------------- preprocessing ------------------------------------------
// hist: count in-degree AND record each edge's within-node rank (the atomic's
// return value) so the placement pass needs no atomics at all.
__global__ void hist_kernel(const int* __restrict__ dst) {
    int i = blockIdx.x * blockDim.x + threadIdx.x;
    if (i * 8 < N_EDGES) {
        int4 a = *(const int4*)(dst + i * 8);
        int4 b = *(const int4*)(dst + i * 8 + 4);
        int r0 = atomicAdd(&g_counts[a.x], 1);
        int r1 = atomicAdd(&g_counts[a.y], 1);
        int r2 = atomicAdd(&g_counts[a.z], 1);
        int r3 = atomicAdd(&g_counts[a.w], 1);
        int r4 = atomicAdd(&g_counts[b.x], 1);
        int r5 = atomicAdd(&g_counts[b.y], 1);
        int r6 = atomicAdd(&g_counts[b.z], 1);
        int r7 = atomicAdd(&g_counts[b.w], 1);
        *(int4*)(g_rank + i * 8)     = make_int4(r0, r1, r2, r3);
        *(int4*)(g_rank + i * 8 + 4) = make_int4(r4, r5, r6, r7);
    }
}

__global__ void prefix_kernel() {
    __shared__ int sh[256];
    __shared__ int block_base;
    int i = blockIdx.x * 256 + threadIdx.x;
    int c = (i < N_NODES) ? g_counts[i] : 0;
    int v = c;
    sh[threadIdx.x] = v;
    __syncthreads();
    #pragma unroll
    for (int off = 1; off < 256; off <<= 1) {
        int t = (threadIdx.x >= off) ? sh[threadIdx.x - off] : 0;
        __syncthreads();
        v += t;
        sh[threadIdx.x] = v;
        __syncthreads();
    }
    if (threadIdx.x == 255) block_base = atomicAdd(&g_counts[N_NODES], v);
    __syncthreads();
    if (i < N_NODES) {
        g_base[i] = block_base + v - c;
        g_dis[i]  = rsqrtf((float)c + 1.0f);
    }
}

// placement: pos = base[dst] + rank  (pure loads + scattered store, no atomics)
__global__ void place_kernel(const int* __restrict__ src,
                             const int* __restrict__ dst) {
    int i = blockIdx.x * blockDim.x + threadIdx.x;
    if (i * 8 < N_EDGES) {
        int4 sa = *(const int4*)(src + i * 8);
        int4 sb = *(const int4*)(src + i * 8 + 4);
        int4 da = *(const int4*)(dst + i * 8);
        int4 db = *(const int4*)(dst + i * 8 + 4);
        int4 ra = *(const int4*)(g_rank + i * 8);
        int4 rb = *(const int4*)(g_rank + i * 8 + 4);
        g_csr_src[__ldg(&g_base[da.x]) + ra.x] = sa.x;
        g_csr_src[__ldg(&g_base[da.y]) + ra.y] = sa.y;
        g_csr_src[__ldg(&g_base[da.z]) + ra.z] = sa.z;
        g_csr_src[__ldg(&g_base[da.w]) + ra.w] = sa.w;
        g_csr_src[__ldg(&g_base[db.x]) + rb.x] = sb.x;
        g_csr_src[__ldg(&g_base[db.y]) + rb.y] = sb.y;
        g_csr_src[__ldg(&g_base[db.z]) + rb.z] = sb.z;
        g_csr_src[__ldg(&g_base[db.w]) + rb.w] = sb.w;
    }
}

// W^T fp16 prep: Wt[layer][n][k] = (half)W[k][n], both layers in one launch.
__global__ void prep_wt_kernel(const float* __restrict__ W1,
                               const float* __restrict__ W2) {
    int i = blockIdx.x * blockDim.x + threadIdx.x;   // 8 elements each
    int e = i * 8;
    if (e >= 2 * D * D) return;
    int layer = e >= D * D;
    const float* W = layer ? W2 : W1;
    int li = e - layer * D * D;
    int n = li >> 7, k0 = li & 127;
    __half2 p[4];
    #pragma unroll
    for (int j = 0; j < 4; j++) {
        float a = W[(size_t)(k0 + 2 * j) * D + n];
        float b = W[(size_t)(k0 + 2 * j + 1) * D + n];
        p[j] = __floats2half2_rn(a, b);
    }
    *(uint4*)(&g_wt[layer][li]) = make_uint4(
        *(uint32_t*)&p[0], *(uint32_t*)&p[1], *(uint32_t*)&p[2], *(uint32_t*)&p[3]);
}

// ---------------- fp16 GEMM: full-K resident, N=128 per CTA ---------------
// OUT(fp16)[r][c] = (A[M,128] @ W[128,128])[r][c] * g_dis[r]
// A staged ONCE; B from pre-transposed fp16 Wt (coalesced uint4 loads).

__device__ __forceinline__ void ldsm_x4(uint32_t& r0, uint32_t& r1, uint32_t& r2,
                                        uint32_t& r3, uint32_t addr) {
    asm volatile("ldmatrix.sync.aligned.m8n8.x4.shared.b16 {%0,%1,%2,%3}, [%4];"
                 : "=r"(r0), "=r"(r1), "=r"(r2), "=r"(r3) : "r"(addr));
}

__device__ __forceinline__ void mma_f16(float4& d, const uint32_t* a, const uint32_t* b) {
    asm volatile(
        "mma.sync.aligned.m16n8k16.row.col.f32.f16.f16.f32 "
        "{%0,%1,%2,%3}, {%4,%5,%6,%7}, {%8,%9}, {%0,%1,%2,%3};"
        : "+f"(d.x), "+f"(d.y), "+f"(d.z), "+f"(d.w)
        : "r"(a[0]), "r"(a[1]), "r"(a[2]), "r"(a[3]), "r"(b[0]), "r"(b[1]));
}

// stage layout (bytes): A [128 rows x 48B] = 6144, B [128 nrows x 48B] = 6144
#define B_BASE      6144
#define STAGE_BYTES 12288
#define GEMM_SMEM   (8 * STAGE_BYTES)   // 96 KB

template <bool A_F16>
__global__ __launch_bounds__(256, 2)
void gemm_1t(const float* __restrict__ Xf, const __half* __restrict__ Xh,
             const __half* __restrict__ Wt, __half* __restrict__ OUT, int M) {
    extern __shared__ __align__(16) char smem[];
    uint32_t sm = (uint32_t)__cvta_generic_to_shared(smem);

    int tid = threadIdx.x;
    int wid = tid >> 5, lane = tid & 31;
    int wm = wid >> 1, wn = wid & 1;
    int g = lane >> 2, t = lane & 3;
    int block_row = blockIdx.x * 128;

    // A load coordinates
    int a_r0 = tid >> 2;
    int a_c4 = (tid & 3) * 4;
    int a_r16 = tid >> 1;
    int a_h16 = tid & 1;

    int gr0, gr1;
    const float*  Xp0 = nullptr; const float* Xp1 = nullptr;
    const __half* Xph = nullptr;
    uint32_t a_st0 = 0, a_st1 = 0, a_st16 = 0;
    if (A_F16) {
        gr0 = block_row + a_r16; gr1 = 0;
        Xph = Xh + (size_t)gr0 * D + a_h16 * 8;
        a_st16 = sm + a_r16 * 48 + a_h16 * 16;
    } else {
        gr0 = block_row + a_r0; gr1 = gr0 + 64;
        Xp0 = Xf + (size_t)gr0 * D + a_c4;
        Xp1 = Xf + (size_t)gr1 * D + a_c4;
        a_st0 = sm + a_r0 * 48 + a_c4 * 2;
        a_st1 = sm + (a_r0 + 64) * 48 + a_c4 * 2;
    }

    // B load coordinates: thread covers n-row tid>>1, k-half (tid&1)*8
    int b_n = tid >> 1;
    int b_h = tid & 1;
    const __half* Wtp = Wt + (size_t)b_n * D + b_h * 8;
    uint32_t b_st = sm + B_BASE + b_n * 48 + b_h * 16;

    // ldmatrix per-lane addresses
    uint32_t a_ld, b_ld;
    {
        int arow = wm * 32 + (lane & 7) + ((lane >> 3) & 1) * 8;
        int abyte = ((lane >> 4) & 1) * 16;
        a_ld = sm + arow * 48 + abyte;
        int m = lane >> 3;
        int nrow = wn * 32 + (m >> 1) * 8 + (lane & 7);
        int kb = (m & 1) * 16;
        b_ld = sm + B_BASE + nrow * 48 + kb;
    }

    // ---- load phase: all 8 chunks (A once, B full 128 cols), coalesced ----
    #pragma unroll
    for (int c = 0; c < 8; c++) {
        uint32_t ofs = (uint32_t)(c * STAGE_BYTES);
        int kc = c * 16;
        if (A_F16) {
            uint4 vAh = (gr0 < M) ? *(const uint4*)(Xph + kc) : make_uint4(0, 0, 0, 0);
            asm volatile("st.shared.v4.b32 [%0], {%1,%2,%3,%4};"
                :: "r"(a_st16 + ofs), "r"(vAh.x), "r"(vAh.y), "r"(vAh.z), "r"(vAh.w));
        } else {
            float4 vA0 = (gr0 < M) ? *(const float4*)(Xp0 + kc)
                                   : make_float4(0.f, 0.f, 0.f, 0.f);
            float4 vA1 = (gr1 < M) ? *(const float4*)(Xp1 + kc)
                                   : make_float4(0.f, 0.f, 0.f, 0.f);
            __half2 h01 = __floats2half2_rn(vA0.x, vA0.y);
            __half2 h23 = __floats2half2_rn(vA0.z, vA0.w);
            asm volatile("st.shared.v2.b32 [%0], {%1,%2};"
                :: "r"(a_st0 + ofs), "r"(*(uint32_t*)&h01), "r"(*(uint32_t*)&h23));
            h01 = __floats2half2_rn(vA1.x, vA1.y);
            h23 = __floats2half2_rn(vA1.z, vA1.w);
            asm volatile("st.shared.v2.b32 [%0], {%1,%2};"
                :: "r"(a_st1 + ofs), "r"(*(uint32_t*)&h01), "r"(*(uint32_t*)&h23));
        }
        uint4 vB = *(const uint4*)(Wtp + kc);
        asm volatile("st.shared.v4.b32 [%0], {%1,%2,%3,%4};"
            :: "r"(b_st + ofs), "r"(vB.x), "r"(vB.y), "r"(vB.z), "r"(vB.w));
    }

    __syncthreads();   // the only barrier

    // ---- compute: two n-halves over resident A, barrier-free ----
    #pragma unroll
    for (int nh = 0; nh < 2; nh++) {
        float4 acc[2][4];
        #pragma unroll
        for (int mt = 0; mt < 2; mt++)
            #pragma unroll
            for (int nt = 0; nt < 4; nt++)
                acc[mt][nt] = make_float4(0.f, 0.f, 0.f, 0.f);

        uint32_t b_half = b_ld + nh * (64 * 48);

        #pragma unroll
        for (int c = 0; c < 8; c++) {
            uint32_t cb = (uint32_t)(c * STAGE_BYTES);
            uint32_t ah[2][4], bh[4][2];
            ldsm_x4(ah[0][0], ah[0][1], ah[0][2], ah[0][3], a_ld + cb);
            ldsm_x4(ah[1][0], ah[1][1], ah[1][2], ah[1][3], a_ld + cb + 768);
            ldsm_x4(bh[0][0], bh[0][1], bh[1][0], bh[1][1], b_half + cb);
            ldsm_x4(bh[2][0], bh[2][1], bh[3][0], bh[3][1], b_half + cb + 768);

            #pragma unroll
            for (int mt = 0; mt < 2; mt++)
                #pragma unroll
                for (int nt = 0; nt < 4; nt++)
                    mma_f16(acc[mt][nt], ah[mt], bh[nt]);
        }

        // epilogue for this half: scale rows by dis, store fp16
        #pragma unroll
        for (int mt = 0; mt < 2; mt++) {
            int r0 = block_row + wm * 32 + mt * 16 + g;
            int r1 = r0 + 8;
            float d0 = (r0 < M) ? g_dis[r0] : 0.f;
            float d1 = (r1 < M) ? g_dis[r1] : 0.f;
            #pragma unroll
            for (int nt = 0; nt < 4; nt++) {
                int col = nh * 64 + wn * 32 + nt * 8 + 2 * t;
                float4 c = acc[mt][nt];
                if (r0 < M)
                    *(__half2*)(OUT + (size_t)r0 * D + col) =
                        __floats2half2_rn(c.x * d0, c.y * d0);
                if (r1 < M)
                    *(__half2*)(OUT + (size_t)r1 * D + col) =
                        __floats2half2_rn(c.z * d1, c.w * d1);
            }
        }
    }
}

// ---------------- aggregation (warp per node), F=128, fp16 gathers --------
template <bool FUSE_GEMV>
__global__ __launch_bounds__(256)
void agg128_kernel(const __half* __restrict__ HW, const float* __restrict__ bias,
                   __half* __restrict__ OUTH, const float* __restrict__ W3) {
    int warp = (blockIdx.x * blockDim.x + threadIdx.x) >> 5;
    int lane = threadIdx.x & 31;
    if (warp >= N_NODES) return;
    int node = warp;

    const uint2* rowp = (const uint2*)(HW + (size_t)node * D) + lane;
    uint2 sv = *rowp;
    float2 a0 = __half22float2(*(const __half2*)&sv.x);
    float2 a1 = __half22float2(*(const __half2*)&sv.y);
    float4 acc = make_float4(a0.x, a0.y, a1.x, a1.y);

    int beg = g_base[node];
    int end = beg + g_counts[node];
    int e = beg;
    for (; e + 2 <= end; e += 2) {
        int s0 = __ldg(&g_csr_src[e]);
        int s1 = __ldg(&g_csr_src[e + 1]);
        uint2 v0 = *((const uint2*)(HW + (size_t)s0 * D) + lane);
        uint2 v1 = *((const uint2*)(HW + (size_t)s1 * D) + lane);
        float2 f00 = __half22float2(*(const __half2*)&v0.x);
        float2 f01 = __half22float2(*(const __half2*)&v0.y);
        float2 f10 = __half22float2(*(const __half2*)&v1.x);
        float2 f11 = __half22float2(*(const __half2*)&v1.y);
        acc.x += f00.x + f10.x; acc.y += f00.y + f10.y;
        acc.z += f01.x + f11.x; acc.w += f01.y + f11.y;
    }
    if (e < end) {
        int s = __ldg(&g_csr_src[e]);
        uint2 v = *((const uint2*)(HW + (size_t)s * D) + lane);
        float2 f0 = __half22float2(*(const __half2*)&v.x);
        float2 f1 = __half22float2(*(const __half2*)&v.y);
        acc.x += f0.x; acc.y += f0.y; acc.z += f1.x; acc.w += f1.y;
    }

    float dn = g_dis[node];
    float4 b = ((const float4*)bias)[lane];
    acc.x = fmaxf(acc.x * dn + b.x, 0.f);
    acc.y = fmaxf(acc.y * dn + b.y, 0.f);
    acc.z = fmaxf(acc.z * dn + b.z, 0.f);
    acc.w = fmaxf(acc.w * dn + b.w, 0.f);

    if (FUSE_GEMV) {
        float4 w = ((const float4*)W3)[lane];
        float dot = acc.x * w.x + acc.y * w.y + acc.z * w.z + acc.w * w.w;
        #pragma unroll
        for (int off = 16; off > 0; off >>= 1)
            dot += __shfl_down_sync(0xFFFFFFFFu, dot, off);
        if (lane == 0) g_hw3[node] = dot * dn;
    } else {
        __half2 h01 = __floats2half2_rn(acc.x, acc.y);
        __half2 h23 = __floats2half2_rn(acc.z, acc.w);
        ((uint2*)(OUTH + (size_t)node * D))[lane] =
            make_uint2(*(uint32_t*)&h01, *(uint32_t*)&h23);
    }
}

// ---------------- layer 3: scalar aggregation -----------------------------
__global__ void agg3_kernel(const float* __restrict__ b3, float* __restrict__ OUT) {
    int node = blockIdx.x * blockDim.x + threadIdx.x;
    if (node >= N_NODES) return;
    float acc = g_hw3[node];
    int beg = g_base[node];
    int end = beg + g_counts[node];
    for (int e = beg; e < end; e++)
        acc += g_hw3[__ldg(&g_csr_src[e])];
    OUT[node] = fmaxf(acc * g_dis[node] + b3[0], 0.f);
}

// ---------------- launch ---------------------------------------------------
extern "C" void kernel_launch(void* const* d_in, const int* in_sizes, int n_in,
                              void* d_out, int out_size) {
    const float* x  = (const float*)d_in[0];
    const int*   ei = (const int*)d_in[1];
    const float* W1 = (const float*)d_in[2];
    const float* b1 = (const float*)d_in[3];
    const float* W2 = (const float*)d_in[4];
    const float* b2 = (const float*)d_in[5];
    const float* W3 = (const float*)d_in[6];
    const float* b3 = (const float*)d_in[7];
    float* out = (float*)d_out;

    const int* src = ei;
    const int* dst = ei + N_EDGES;

    __half *hw, *acth, *wt;
    cudaGetSymbolAddress((void**)&hw,   g_hw);
    cudaGetSymbolAddress((void**)&acth, g_acth);
    cudaGetSymbolAddress((void**)&wt,   g_wt);
    int* counts; cudaGetSymbolAddress((void**)&counts, g_counts);

    static bool attr_set = false;
    if (!attr_set) {
        cudaFuncSetAttribute(gemm_1t<false>,
                             cudaFuncAttributeMaxDynamicSharedMemorySize, GEMM_SMEM);
        cudaFuncSetAttribute(gemm_1t<true>,
                             cudaFuncAttributeMaxDynamicSharedMemorySize, GEMM_SMEM);
        attr_set = true;
    }

    int nb_nodes = (N_NODES + 255) / 256;
    int nb_edge8 = (N_EDGES / 8 + 255) / 256;
    int nb_warp  = (N_NODES * 32 + 255) / 256;
    int nb_gemm  = (N_NODES + 127) / 128;

    // W^T prep (independent of everything else; tiny)
    prep_wt_kernel<<<(2 * D * D / 8 + 255) / 256, 256>>>(W1, W2);

    // preprocessing: unordered CSR by dst (rank-based, atomic-free placement)
    cudaMemsetAsync(counts, 0, (N_NODES + 1) * sizeof(int));
    hist_kernel<<<nb_edge8, 256>>>(dst);
    prefix_kernel<<<nb_nodes, 256>>>();
    place_kernel<<<nb_edge8, 256>>>(src, dst);

    // layer 1 (A = x fp32, converted inline)
    gemm_1t<false><<<nb_gemm, 256, GEMM_SMEM>>>(x, nullptr, wt, hw, N_NODES);
    agg128_kernel<false><<<nb_warp, 256>>>(hw, b1, acth, nullptr);
    // layer 2 (A = act fp16 direct) + fused layer-3 GEMV
    gemm_1t<true><<<nb_gemm, 256, GEMM_SMEM>>>(nullptr, acth, wt + D * D, hw, N_NODES);
    agg128_kernel<true><<<nb_warp, 256>>>(hw, b2, nullptr, W3);
    // layer 3 aggregation
    agg3_kernel<<<nb_nodes, 256>>>(b3, out);
}

// round 15
// speedup vs baseline: 1.0280x; 1.0280x over previous
#include <cuda_runtime.h>
#include <cuda_fp16.h>
#include <cstdint>

#define N_NODES 50000
#define N_EDGES 600000
#define D 128

// ---------------- scratch (static device globals; no allocation) ----------
__device__ float  g_dis[N_NODES];
__device__ int    g_counts[N_NODES + 1];         // [N_NODES] = running total
__device__ int    g_base[N_NODES];
__device__ int    g_rank[N_EDGES];               // within-dst rank per edge
__device__ int    g_csr_src[N_EDGES];
__device__ __half g_hw[(size_t)N_NODES * D];     // hw' (dis-scaled) fp16
__device__ __half g_acth[(size_t)N_NODES * D];   // activation fp16
__device__ float  g_hw3[N_NODES];

// ---------------- preprocessing ------------------------------------------
// hist: count in-degree AND record each edge's within-node rank (the atomic's
// return value) so the placement pass needs no atomics at all. 4 edges/thread.
__global__ void hist_kernel(const int* __restrict__ dst) {
    int i = blockIdx.x * blockDim.x + threadIdx.x;
    if (i * 4 < N_EDGES) {
        int4 a = *(const int4*)(dst + i * 4);
        int r0 = atomicAdd(&g_counts[a.x], 1);
        int r1 = atomicAdd(&g_counts[a.y], 1);
        int r2 = atomicAdd(&g_counts[a.z], 1);
        int r3 = atomicAdd(&g_counts[a.w], 1);
        *(int4*)(g_rank + i * 4) = make_int4(r0, r1, r2, r3);
    }
}

__global__ void prefix_kernel() {
    __shared__ int sh[256];
    __shared__ int block_base;
    int i = blockIdx.x * 256 + threadIdx.x;
    int c = (i < N_NODES) ? g_counts[i] : 0;
    int v = c;
    sh[threadIdx.x] = v;
    __syncthreads();
    #pragma unroll
    for (int off = 1; off < 256; off <<= 1) {
        int t = (threadIdx.x >= off) ? sh[threadIdx.x - off] : 0;
        __syncthreads();
        v += t;
        sh[threadIdx.x] = v;
        __syncthreads();
    }
    if (threadIdx.x == 255) block_base = atomicAdd(&g_counts[N_NODES], v);
    __syncthreads();
    if (i < N_NODES) {
        g_base[i] = block_base + v - c;
        g_dis[i]  = rsqrtf((float)c + 1.0f);
    }
}

// placement: pos = base[dst] + rank (no atomics). 2 edges/thread for high
// thread-level parallelism — the dependent chain (dst -> base[dst] -> store)
// is latency-bound, so we want many chains in flight per SM.
__global__ void place_kernel(const int* __restrict__ src,
                             const int* __restrict__ dst) {
    int i = blockIdx.x * blockDim.x + threadIdx.x;
    if (i * 2 < N_EDGES) {
        int2 s2 = *(const int2*)(src + i * 2);
        int2 d2 = *(const int2*)(dst + i * 2);
        int2 r2 = *(const int2*)(g_rank + i * 2);
        g_csr_src[__ldg(&g_base[d2.x]) + r2.x] = s2.x;
        g_csr_src[__ldg(&g_base[d2.y]) + r2.y] = s2.y;
    }
}

// ---------------- fp16 GEMM: full-K resident, N=128 per CTA ---------------
// OUT(fp16)[r][c] = (A[M,128] @ W[128,128])[r][c] * g_dis[r]
// A staged ONCE; two barrier-free compute sweeps (n-halves) reuse acc regs.

__device__ __forceinline__ void ldsm_x4(uint32_t& r0, uint32_t& r1, uint32_t& r2,
                                        uint32_t& r3, uint32_t addr) {
    asm volatile("ldmatrix.sync.aligned.m8n8.x4.shared.b16 {%0,%1,%2,%3}, [%4];"
                 : "=r"(r0), "=r"(r1), "=r"(r2), "=r"(r3) : "r"(addr));
}

__device__ __forceinline__ void mma_f16(float4& d, const uint32_t* a, const uint32_t* b) {
    asm volatile(
        "mma.sync.aligned.m16n8k16.row.col.f32.f16.f16.f32 "
        "{%0,%1,%2,%3}, {%4,%5,%6,%7}, {%8,%9}, {%0,%1,%2,%3};"
        : "+f"(d.x), "+f"(d.y), "+f"(d.z), "+f"(d.w)
        : "r"(a[0]), "r"(a[1]), "r"(a[2]), "r"(a[3]), "r"(b[0]), "r"(b[1]));
}

// stage layout (bytes): A [128 rows x 48B] = 6144, B [128 nrows x 48B] = 6144
#define B_BASE      6144
#define STAGE_BYTES 12288
#define GEMM_SMEM   (8 * STAGE_BYTES)   // 96 KB

template <bool A_F16>
__global__ __launch_bounds__(256, 2)
void gemm_1t(const float* __restrict__ Xf, const __half* __restrict__ Xh,
             const float* __restrict__ W, __half* __restrict__ OUT, int M) {
    extern __shared__ __align__(16) char smem[];
    uint32_t sm = (uint32_t)__cvta_generic_to_shared(smem);

    int tid = threadIdx.x;
    int wid = tid >> 5, lane = tid & 31;
    int wm = wid >> 1, wn = wid & 1;
    int g = lane >> 2, t = lane & 3;
    int block_row = blockIdx.x * 128;

    // A load coordinates
    int a_r0 = tid >> 2;
    int a_c4 = (tid & 3) * 4;
    int a_r16 = tid >> 1;
    int a_h16 = tid & 1;

    int gr0, gr1;
    const float*  Xp0 = nullptr; const float* Xp1 = nullptr;
    const __half* Xph = nullptr;
    uint32_t a_st0 = 0, a_st1 = 0, a_st16 = 0;
    if (A_F16) {
        gr0 = block_row + a_r16; gr1 = 0;
        Xph = Xh + (size_t)gr0 * D + a_h16 * 8;
        a_st16 = sm + a_r16 * 48 + a_h16 * 16;
    } else {
        gr0 = block_row + a_r0; gr1 = gr0 + 64;
        Xp0 = Xf + (size_t)gr0 * D + a_c4;
        Xp1 = Xf + (size_t)gr1 * D + a_c4;
        a_st0 = sm + a_r0 * 48 + a_c4 * 2;
        a_st1 = sm + (a_r0 + 64) * 48 + a_c4 * 2;
    }

    // B load coordinates: thread covers n = tid&127, k-subgroup kg = tid>>7
    int b_n  = tid & 127;
    int b_kg = tid >> 7;                 // 0 or 1 -> k0 = kg*8 within chunk
    const float* Wp = W + (size_t)(b_kg * 8) * D + b_n;
    uint32_t b_st = sm + B_BASE + b_n * 48 + b_kg * 16;

    // ldmatrix per-lane addresses
    uint32_t a_ld, b_ld;
    {
        int arow = wm * 32 + (lane & 7) + ((lane >> 3) & 1) * 8;
        int abyte = ((lane >> 4) & 1) * 16;
        a_ld = sm + arow * 48 + abyte;
        int m = lane >> 3;
        int nrow = wn * 32 + (m >> 1) * 8 + (lane & 7);
        int kb = (m & 1) * 16;
        b_ld = sm + B_BASE + nrow * 48 + kb;
    }

    // ---- load phase: all 8 chunks (A once, B full 128 cols) ----
    #pragma unroll
    for (int c = 0; c < 8; c++) {
        uint32_t ofs = (uint32_t)(c * STAGE_BYTES);
        int kc = c * 16;
        if (A_F16) {
            uint4 vAh = (gr0 < M) ? *(const uint4*)(Xph + kc) : make_uint4(0, 0, 0, 0);
            asm volatile("st.shared.v4.b32 [%0], {%1,%2,%3,%4};"
                :: "r"(a_st16 + ofs), "r"(vAh.x), "r"(vAh.y), "r"(vAh.z), "r"(vAh.w));
        } else {
            float4 vA0 = (gr0 < M) ? *(const float4*)(Xp0 + kc)
                                   : make_float4(0.f, 0.f, 0.f, 0.f);
            float4 vA1 = (gr1 < M) ? *(const float4*)(Xp1 + kc)
                                   : make_float4(0.f, 0.f, 0.f, 0.f);
            __half2 h01 = __floats2half2_rn(vA0.x, vA0.y);
            __half2 h23 = __floats2half2_rn(vA0.z, vA0.w);
            asm volatile("st.shared.v2.b32 [%0], {%1,%2};"
                :: "r"(a_st0 + ofs), "r"(*(uint32_t*)&h01), "r"(*(uint32_t*)&h23));
            h01 = __floats2half2_rn(vA1.x, vA1.y);
            h23 = __floats2half2_rn(vA1.z, vA1.w);
            asm volatile("st.shared.v2.b32 [%0], {%1,%2};"
                :: "r"(a_st1 + ofs), "r"(*(uint32_t*)&h01), "r"(*(uint32_t*)&h23));
        }
        // B: 8 strided W values for (n, k0..k0+7)
        const float* wp = Wp + (size_t)kc * D;
        float w0 = wp[0],     w1 = wp[D],     w2 = wp[2 * D], w3 = wp[3 * D];
        float w4 = wp[4 * D], w5 = wp[5 * D], w6 = wp[6 * D], w7 = wp[7 * D];
        __half2 p0 = __floats2half2_rn(w0, w1);
        __half2 p1 = __floats2half2_rn(w2, w3);
        __half2 p2 = __floats2half2_rn(w4, w5);
        __half2 p3 = __floats2half2_rn(w6, w7);
        asm volatile("st.shared.v4.b32 [%0], {%1,%2,%3,%4};"
            :: "r"(b_st + ofs), "r"(*(uint32_t*)&p0), "r"(*(uint32_t*)&p1),
               "r"(*(uint32_t*)&p2), "r"(*(uint32_t*)&p3));
    }

    __syncthreads();   // the only barrier

    // ---- compute: two n-halves over resident A, barrier-free ----
    #pragma unroll
    for (int nh = 0; nh < 2; nh++) {
        float4 acc[2][4];
        #pragma unroll
        for (int mt = 0; mt < 2; mt++)
            #pragma unroll
            for (int nt = 0; nt < 4; nt++)
                acc[mt][nt] = make_float4(0.f, 0.f, 0.f, 0.f);

        uint32_t b_half = b_ld + nh * (64 * 48);

        #pragma unroll
        for (int c = 0; c < 8; c++) {
            uint32_t cb = (uint32_t)(c * STAGE_BYTES);
            uint32_t ah[2][4], bh[4][2];
            ldsm_x4(ah[0][0], ah[0][1], ah[0][2], ah[0][3], a_ld + cb);
            ldsm_x4(ah[1][0], ah[1][1], ah[1][2], ah[1][3], a_ld + cb + 768);
            ldsm_x4(bh[0][0], bh[0][1], bh[1][0], bh[1][1], b_half + cb);
            ldsm_x4(bh[2][0], bh[2][1], bh[3][0], bh[3][1], b_half + cb + 768);

            #pragma unroll
            for (int mt = 0; mt < 2; mt++)
                #pragma unroll
                for (int nt = 0; nt < 4; nt++)
                    mma_f16(acc[mt][nt], ah[mt], bh[nt]);
        }

        // epilogue for this half: scale rows by dis, store fp16
        #pragma unroll
        for (int mt = 0; mt < 2; mt++) {
            int r0 = block_row + wm * 32 + mt * 16 + g;
            int r1 = r0 + 8;
            float d0 = (r0 < M) ? g_dis[r0] : 0.f;
            float d1 = (r1 < M) ? g_dis[r1] : 0.f;
            #pragma unroll
            for (int nt = 0; nt < 4; nt++) {
                int col = nh * 64 + wn * 32 + nt * 8 + 2 * t;
                float4 c = acc[mt][nt];
                if (r0 < M)
                    *(__half2*)(OUT + (size_t)r0 * D + col) =
                        __floats2half2_rn(c.x * d0, c.y * d0);
                if (r1 < M)
                    *(__half2*)(OUT + (size_t)r1 * D + col) =
                        __floats2half2_rn(c.z * d1, c.w * d1);
            }
        }
    }
}

// ---------------- aggregation (warp per node), F=128, fp16 gathers --------
template <bool FUSE_GEMV>
__global__ __launch_bounds__(256)
void agg128_kernel(const __half* __restrict__ HW, const float* __restrict__ bias,
                   __half* __restrict__ OUTH, const float* __restrict__ W3) {
    int warp = (blockIdx.x * blockDim.x + threadIdx.x) >> 5;
    int lane = threadIdx.x & 31;
    if (warp >= N_NODES) return;
    int node = warp;

    const uint2* rowp = (const uint2*)(HW + (size_t)node * D) + lane;
    uint2 sv = *rowp;
    float2 a0 = __half22float2(*(const __half2*)&sv.x);
    float2 a1 = __half22float2(*(const __half2*)&sv.y);
    float4 acc = make_float4(a0.x, a0.y, a1.x, a1.y);

    int beg = g_base[node];
    int end = beg + g_counts[node];
    int e = beg;
    for (; e + 2 <= end; e += 2) {
        int s0 = __ldg(&g_csr_src[e]);
        int s1 = __ldg(&g_csr_src[e + 1]);
        uint2 v0 = *((const uint2*)(HW + (size_t)s0 * D) + lane);
        uint2 v1 = *((const uint2*)(HW + (size_t)s1 * D) + lane);
        float2 f00 = __half22float2(*(const __half2*)&v0.x);
        float2 f01 = __half22float2(*(const __half2*)&v0.y);
        float2 f10 = __half22float2(*(const __half2*)&v1.x);
        float2 f11 = __half22float2(*(const __half2*)&v1.y);
        acc.x += f00.x + f10.x; acc.y += f00.y + f10.y;
        acc.z += f01.x + f11.x; acc.w += f01.y + f11.y;
    }
    if (e < end) {
        int s = __ldg(&g_csr_src[e]);
        uint2 v = *((const uint2*)(HW + (size_t)s * D) + lane);
        float2 f0 = __half22float2(*(const __half2*)&v.x);
        float2 f1 = __half22float2(*(const __half2*)&v.y);
        acc.x += f0.x; acc.y += f0.y; acc.z += f1.x; acc.w += f1.y;
    }

    float dn = g_dis[node];
    float4 b = ((const float4*)bias)[lane];
    acc.x = fmaxf(acc.x * dn + b.x, 0.f);
    acc.y = fmaxf(acc.y * dn + b.y, 0.f);
    acc.z = fmaxf(acc.z * dn + b.z, 0.f);
    acc.w = fmaxf(acc.w * dn + b.w, 0.f);

    if (FUSE_GEMV) {
        float4 w = ((const float4*)W3)[lane];
        float dot = acc.x * w.x + acc.y * w.y + acc.z * w.z + acc.w * w.w;
        #pragma unroll
        for (int off = 16; off > 0; off >>= 1)
            dot += __shfl_down_sync(0xFFFFFFFFu, dot, off);
        if (lane == 0) g_hw3[node] = dot * dn;
    } else {
        __half2 h01 = __floats2half2_rn(acc.x, acc.y);
        __half2 h23 = __floats2half2_rn(acc.z, acc.w);
        ((uint2*)(OUTH + (size_t)node * D))[lane] =
            make_uint2(*(uint32_t*)&h01, *(uint32_t*)&h23);
    }
}

// ---------------- layer 3: scalar aggregation -----------------------------
__global__ void agg3_kernel(const float* __restrict__ b3, float* __restrict__ OUT) {
    int node = blockIdx.x * blockDim.x + threadIdx.x;
    if (node >= N_NODES) return;
    float acc = g_hw3[node];
    int beg = g_base[node];
    int end = beg + g_counts[node];
    for (int e = beg; e < end; e++)
        acc += g_hw3[__ldg(&g_csr_src[e])];
    OUT[node] = fmaxf(acc * g_dis[node] + b3[0], 0.f);
}

// ---------------- launch ---------------------------------------------------
extern "C" void kernel_launch(void* const* d_in, const int* in_sizes, int n_in,
                              void* d_out, int out_size) {
    const float* x  = (const float*)d_in[0];
    const int*   ei = (const int*)d_in[1];
    const float* W1 = (const float*)d_in[2];
    const float* b1 = (const float*)d_in[3];
    const float* W2 = (const float*)d_in[4];
    const float* b2 = (const float*)d_in[5];
    const float* W3 = (const float*)d_in[6];
    const float* b3 = (const float*)d_in[7];
    float* out = (float*)d_out;

    const int* src = ei;
    const int* dst = ei + N_EDGES;

    __half *hw, *acth;
    cudaGetSymbolAddress((void**)&hw,   g_hw);
    cudaGetSymbolAddress((void**)&acth, g_acth);
    int* counts; cudaGetSymbolAddress((void**)&counts, g_counts);

    static bool attr_set = false;
    if (!attr_set) {
        cudaFuncSetAttribute(gemm_1t<false>,
                             cudaFuncAttributeMaxDynamicSharedMemorySize, GEMM_SMEM);
        cudaFuncSetAttribute(gemm_1t<true>,
                             cudaFuncAttributeMaxDynamicSharedMemorySize, GEMM_SMEM);
        attr_set = true;
    }

    int nb_nodes = (N_NODES + 255) / 256;
    int nb_edge4 = (N_EDGES / 4 + 255) / 256;
    int nb_edge2 = (N_EDGES / 2 + 255) / 256;
    int nb_warp  = (N_NODES * 32 + 255) / 256;
    int nb_gemm  = (N_NODES + 127) / 128;

    // preprocessing: unordered CSR by dst (rank-based, atomic-free placement)
    cudaMemsetAsync(counts, 0, (N_NODES + 1) * sizeof(int));
    hist_kernel<<<nb_edge4, 256>>>(dst);
    prefix_kernel<<<nb_nodes, 256>>>();
    place_kernel<<<nb_edge2, 256>>>(src, dst);

    // layer 1 (A = x fp32, converted inline)
    gemm_1t<false><<<nb_gemm, 256, GEMM_SMEM>>>(x, nullptr, W1, hw, N_NODES);
    agg128_kernel<false><<<nb_warp, 256>>>(hw, b1, acth, nullptr);
    // layer 2 (A = act fp16 direct) + fused layer-3 GEMV
    gemm_1t<true><<<nb_gemm, 256, GEMM_SMEM>>>(nullptr, acth, W2, hw, N_NODES);
    agg128_kernel<true><<<nb_warp, 256>>>(hw, b2, nullptr, W3);
    // layer 3 aggregation
    agg3_kernel<<<nb_nodes, 256>>>(b3, out);
}

// round 17
// speedup vs baseline: 1.0436x; 1.0151x over previous
#include <cuda_runtime.h>
#include <cuda_fp16.h>
#include <cstdint>

#define N_NODES 50000
#define N_EDGES 600000
#define D 128

// ---------------- scratch (static device globals; no allocation) ----------
__device__ float  g_dis[N_NODES];
__device__ int    g_counts[N_NODES + 1];         // [N_NODES] = running total
__device__ int    g_base[N_NODES];
__device__ int    g_rank[N_EDGES];               // within-dst rank per edge
__device__ int    g_csr_src[N_EDGES];
__device__ __half g_hw[(size_t)N_NODES * D];     // hw' (dis-scaled) fp16
__device__ __half g_acth[(size_t)N_NODES * D];   // activation fp16
__device__ float  g_hw3[N_NODES];

// ---------------- preprocessing ------------------------------------------
__global__ void hist_kernel(const int* __restrict__ dst) {
    int i = blockIdx.x * blockDim.x + threadIdx.x;
    if (i * 4 < N_EDGES) {
        int4 a = *(const int4*)(dst + i * 4);
        int r0 = atomicAdd(&g_counts[a.x], 1);
        int r1 = atomicAdd(&g_counts[a.y], 1);
        int r2 = atomicAdd(&g_counts[a.z], 1);
        int r3 = atomicAdd(&g_counts[a.w], 1);
        *(int4*)(g_rank + i * 4) = make_int4(r0, r1, r2, r3);
    }
}

__global__ void prefix_kernel() {
    __shared__ int sh[256];
    __shared__ int block_base;
    int i = blockIdx.x * 256 + threadIdx.x;
    int c = (i < N_NODES) ? g_counts[i] : 0;
    int v = c;
    sh[threadIdx.x] = v;
    __syncthreads();
    #pragma unroll
    for (int off = 1; off < 256; off <<= 1) {
        int t = (threadIdx.x >= off) ? sh[threadIdx.x - off] : 0;
        __syncthreads();
        v += t;
        sh[threadIdx.x] = v;
        __syncthreads();
    }
    if (threadIdx.x == 255) block_base = atomicAdd(&g_counts[N_NODES], v);
    __syncthreads();
    if (i < N_NODES) {
        g_base[i] = block_base + v - c;
        g_dis[i]  = rsqrtf((float)c + 1.0f);
    }
}

__global__ void place_kernel(const int* __restrict__ src,
                             const int* __restrict__ dst) {
    int i = blockIdx.x * blockDim.x + threadIdx.x;
    if (i * 2 < N_EDGES) {
        int2 s2 = *(const int2*)(src + i * 2);
        int2 d2 = *(const int2*)(dst + i * 2);
        int2 r2 = *(const int2*)(g_rank + i * 2);
        g_csr_src[__ldg(&g_base[d2.x]) + r2.x] = s2.x;
        g_csr_src[__ldg(&g_base[d2.y]) + r2.y] = s2.y;
    }
}

// ---------------- fp16 GEMM: SW128 blocked-atom smem, 3 CTAs/SM -----------
// OUT(fp16)[r][c] = (A[M,128] @ W[128,128])[r][c] * g_dis[r]
// Layout (per 128x128 fp16 tile): blk = (row>>3) + (colbytes>>7)*16
//   addr = blk*1024 + (row&7)*128 + ((colbytes&127) ^ ((row&7)<<4))
// XOR applies ONLY to the within-row byte component (no carries, no sm bits).
// A region [0,32KB), B region [32KB,64KB) stored [k][n]. 64KB -> 3 CTAs/SM,
// grid 391 <= 444: single wave.

__device__ __forceinline__ void ldsm_x4(uint32_t& r0, uint32_t& r1, uint32_t& r2,
                                        uint32_t& r3, uint32_t addr) {
    asm volatile("ldmatrix.sync.aligned.m8n8.x4.shared.b16 {%0,%1,%2,%3}, [%4];"
                 : "=r"(r0), "=r"(r1), "=r"(r2), "=r"(r3) : "r"(addr));
}
__device__ __forceinline__ void ldsm_x4_t(uint32_t& r0, uint32_t& r1, uint32_t& r2,
                                          uint32_t& r3, uint32_t addr) {
    asm volatile("ldmatrix.sync.aligned.m8n8.x4.trans.shared.b16 {%0,%1,%2,%3}, [%4];"
                 : "=r"(r0), "=r"(r1), "=r"(r2), "=r"(r3) : "r"(addr));
}
__device__ __forceinline__ void mma_f16(float4& d, const uint32_t* a, const uint32_t* b) {
    asm volatile(
        "mma.sync.aligned.m16n8k16.row.col.f32.f16.f16.f32 "
        "{%0,%1,%2,%3}, {%4,%5,%6,%7}, {%8,%9}, {%0,%1,%2,%3};"
        : "+f"(d.x), "+f"(d.y), "+f"(d.z), "+f"(d.w)
        : "r"(a[0]), "r"(a[1]), "r"(a[2]), "r"(a[3]), "r"(b[0]), "r"(b[1]));
}

#define B_SMEM_OFF 32768u
#define GEMM_SMEM  65536

template <bool A_F16>
__global__ __launch_bounds__(256, 3)
void gemm_1t(const float* __restrict__ Xf, const __half* __restrict__ Xh,
             const float* __restrict__ W, __half* __restrict__ OUT, int M) {
    extern __shared__ __align__(16) char smem[];
    uint32_t sm = (uint32_t)__cvta_generic_to_shared(smem);

    int tid = threadIdx.x;
    int wid = tid >> 5, lane = tid & 31;
    int wm = wid >> 1, wn = wid & 1;
    int g = lane >> 2, t = lane & 3;
    int block_row = blockIdx.x * 128;

    // ================= load phase =================
    if (A_F16) {
        // uint4 flat f = j*256 + tid: row = j*16 + rsub, colhalf = (tid&15)*8
        int rsub = tid >> 4;                       // 0..15
        uint32_t kb = (uint32_t)((tid & 7) * 16);  // colbytes & 127
        uint32_t a_c = sm
            + ((tid >= 128) ? 1024u : 0u)          // (row>>3)&1 component
            + (((tid & 15) >= 8) ? 16384u : 0u)    // colbytes>=128 atom
            + (uint32_t)((rsub & 7) * 128)
            + (kb ^ (uint32_t)((rsub & 7) << 4));
        const __half* Xp = Xh + (size_t)(block_row + rsub) * D + (tid & 15) * 8;
        #pragma unroll
        for (int j = 0; j < 8; j++) {
            int gr = block_row + j * 16 + rsub;
            uint4 v = (gr < M) ? *(const uint4*)(Xp + (size_t)j * 16 * D)
                               : make_uint4(0, 0, 0, 0);
            asm volatile("st.shared.v4.b32 [%0], {%1,%2,%3,%4};"
                :: "r"(a_c + (uint32_t)(j * 2048)), "r"(v.x), "r"(v.y), "r"(v.z), "r"(v.w));
        }
    } else {
        // float4 flat f = j*256 + tid: row = j*8 + warp8, colfloat = (tid&31)*4
        int warp8 = tid >> 5;                      // 0..7 == row&7
        uint32_t kb = (uint32_t)((tid & 15) * 8);  // colbytes & 127
        uint32_t a_c = sm
            + (((tid & 31) >= 16) ? 16384u : 0u)
            + (uint32_t)(warp8 * 128)
            + (kb ^ (uint32_t)(warp8 << 4));
        const float* Xp = Xf + (size_t)(block_row + warp8) * D + (tid & 31) * 4;
        #pragma unroll
        for (int j = 0; j < 16; j++) {
            int gr = block_row + j * 8 + warp8;
            float4 v = (gr < M) ? *(const float4*)(Xp + (size_t)j * 8 * D)
                                : make_float4(0.f, 0.f, 0.f, 0.f);
            __half2 h01 = __floats2half2_rn(v.x, v.y);
            __half2 h23 = __floats2half2_rn(v.z, v.w);
            asm volatile("st.shared.v2.b32 [%0], {%1,%2};"
                :: "r"(a_c + (uint32_t)(j * 1024)),
                   "r"(*(uint32_t*)&h01), "r"(*(uint32_t*)&h23));
        }
    }
    {
        // B: W[k][n] fp32 -> smem [k][n] fp16. row = k = j*8 + warp8,
        // coln = (tid&31)*4 floats -> bytes (tid&31)*8
        int warp8 = tid >> 5;
        uint32_t nb = (uint32_t)((tid & 15) * 8);
        uint32_t b_c = sm + B_SMEM_OFF
            + (((tid & 31) >= 16) ? 16384u : 0u)
            + (uint32_t)(warp8 * 128)
            + (nb ^ (uint32_t)(warp8 << 4));
        const float* Wp = W + (size_t)warp8 * D + (tid & 31) * 4;
        #pragma unroll
        for (int j = 0; j < 16; j++) {
            float4 v = *(const float4*)(Wp + (size_t)j * 8 * D);
            __half2 h01 = __floats2half2_rn(v.x, v.y);
            __half2 h23 = __floats2half2_rn(v.z, v.w);
            asm volatile("st.shared.v2.b32 [%0], {%1,%2};"
                :: "r"(b_c + (uint32_t)(j * 1024)),
                   "r"(*(uint32_t*)&h01), "r"(*(uint32_t*)&h23));
        }
    }

    __syncthreads();   // the only barrier

    // ================= fragment base addresses =================
    int l7 = lane & 7;
    int b3 = (lane >> 3) & 1;
    int b4 = (lane >> 4) & 1;
    // A: row = wm*32 + mt*16 + b3*8 + l7 ; colbytes = c*32 + b4*16
    uint32_t a_row = sm + (uint32_t)((wm * 4 + b3) * 1024 + l7 * 128);
    uint32_t kx[4];
    #pragma unroll
    for (int q = 0; q < 4; q++)
        kx[q] = (uint32_t)((q * 32 + b4 * 16) ^ (l7 << 4));
    // B: krow = c*16 + b3*8 + l7 ; colbytes = nh*128 + wn*64 + v*32 + b4*16
    uint32_t b_row = sm + B_SMEM_OFF + (uint32_t)(b3 * 1024 + l7 * 128);
    uint32_t nx[2];
    #pragma unroll
    for (int v = 0; v < 2; v++)
        nx[v] = (uint32_t)((wn * 64 + v * 32 + b4 * 16) ^ (l7 << 4));

    // ================= compute: two n-halves, barrier-free =================
    #pragma unroll
    for (int nh = 0; nh < 2; nh++) {
        float4 acc[2][4];
        #pragma unroll
        for (int mt = 0; mt < 2; mt++)
            #pragma unroll
            for (int nt = 0; nt < 4; nt++)
                acc[mt][nt] = make_float4(0.f, 0.f, 0.f, 0.f);

        #pragma unroll
        for (int c = 0; c < 8; c++) {
            uint32_t a_c = a_row + (uint32_t)((c >> 2) * 16384) + kx[c & 3];
            uint32_t b_c = b_row + (uint32_t)(c * 2048 + nh * 16384);
            uint32_t ah[2][4], bh[4][2];
            ldsm_x4(ah[0][0], ah[0][1], ah[0][2], ah[0][3], a_c);
            ldsm_x4(ah[1][0], ah[1][1], ah[1][2], ah[1][3], a_c + 2048);
            ldsm_x4_t(bh[0][0], bh[0][1], bh[1][0], bh[1][1], b_c + nx[0]);
            ldsm_x4_t(bh[2][0], bh[2][1], bh[3][0], bh[3][1], b_c + nx[1]);

            #pragma unroll
            for (int mt = 0; mt < 2; mt++)
                #pragma unroll
                for (int nt = 0; nt < 4; nt++)
                    mma_f16(acc[mt][nt], ah[mt], bh[nt]);
        }

        // epilogue for this half: scale rows by dis, store fp16
        #pragma unroll
        for (int mt = 0; mt < 2; mt++) {
            int r0 = block_row + wm * 32 + mt * 16 + g;
            int r1 = r0 + 8;
            float d0 = (r0 < M) ? g_dis[r0] : 0.f;
            float d1 = (r1 < M) ? g_dis[r1] : 0.f;
            #pragma unroll
            for (int nt = 0; nt < 4; nt++) {
                int col = nh * 64 + wn * 32 + nt * 8 + 2 * t;
                float4 c = acc[mt][nt];
                if (r0 < M)
                    *(__half2*)(OUT + (size_t)r0 * D + col) =
                        __floats2half2_rn(c.x * d0, c.y * d0);
                if (r1 < M)
                    *(__half2*)(OUT + (size_t)r1 * D + col) =
                        __floats2half2_rn(c.z * d1, c.w * d1);
            }
        }
    }
}

// ---------------- aggregation (warp per node), F=128, fp16 gathers --------
template <bool FUSE_GEMV>
__global__ __launch_bounds__(256)
void agg128_kernel(const __half* __restrict__ HW, const float* __restrict__ bias,
                   __half* __restrict__ OUTH, const float* __restrict__ W3) {
    int warp = (blockIdx.x * blockDim.x + threadIdx.x) >> 5;
    int lane = threadIdx.x & 31;
    if (warp >= N_NODES) return;
    int node = warp;

    const uint2* rowp = (const uint2*)(HW + (size_t)node * D) + lane;
    uint2 sv = *rowp;
    float2 a0 = __half22float2(*(const __half2*)&sv.x);
    float2 a1 = __half22float2(*(const __half2*)&sv.y);
    float4 acc = make_float4(a0.x, a0.y, a1.x, a1.y);

    int beg = g_base[node];
    int end = beg + g_counts[node];
    int e = beg;
    for (; e + 2 <= end; e += 2) {
        int s0 = __ldg(&g_csr_src[e]);
        int s1 = __ldg(&g_csr_src[e + 1]);
        uint2 v0 = *((const uint2*)(HW + (size_t)s0 * D) + lane);
        uint2 v1 = *((const uint2*)(HW + (size_t)s1 * D) + lane);
        float2 f00 = __half22float2(*(const __half2*)&v0.x);
        float2 f01 = __half22float2(*(const __half2*)&v0.y);
        float2 f10 = __half22float2(*(const __half2*)&v1.x);
        float2 f11 = __half22float2(*(const __half2*)&v1.y);
        acc.x += f00.x + f10.x; acc.y += f00.y + f10.y;
        acc.z += f01.x + f11.x; acc.w += f01.y + f11.y;
    }
    if (e < end) {
        int s = __ldg(&g_csr_src[e]);
        uint2 v = *((const uint2*)(HW + (size_t)s * D) + lane);
        float2 f0 = __half22float2(*(const __half2*)&v.x);
        float2 f1 = __half22float2(*(const __half2*)&v.y);
        acc.x += f0.x; acc.y += f0.y; acc.z += f1.x; acc.w += f1.y;
    }

    float dn = g_dis[node];
    float4 b = ((const float4*)bias)[lane];
    acc.x = fmaxf(acc.x * dn + b.x, 0.f);
    acc.y = fmaxf(acc.y * dn + b.y, 0.f);
    acc.z = fmaxf(acc.z * dn + b.z, 0.f);
    acc.w = fmaxf(acc.w * dn + b.w, 0.f);

    if (FUSE_GEMV) {
        float4 w = ((const float4*)W3)[lane];
        float dot = acc.x * w.x + acc.y * w.y + acc.z * w.z + acc.w * w.w;
        #pragma unroll
        for (int off = 16; off > 0; off >>= 1)
            dot += __shfl_down_sync(0xFFFFFFFFu, dot, off);
        if (lane == 0) g_hw3[node] = dot * dn;
    } else {
        __half2 h01 = __floats2half2_rn(acc.x, acc.y);
        __half2 h23 = __floats2half2_rn(acc.z, acc.w);
        ((uint2*)(OUTH + (size_t)node * D))[lane] =
            make_uint2(*(uint32_t*)&h01, *(uint32_t*)&h23);
    }
}

// ---------------- layer 3: scalar aggregation -----------------------------
__global__ void agg3_kernel(const float* __restrict__ b3, float* __restrict__ OUT) {
    int node = blockIdx.x * blockDim.x + threadIdx.x;
    if (node >= N_NODES) return;
    float acc = g_hw3[node];
    int beg = g_base[node];
    int end = beg + g_counts[node];
    for (int e = beg; e < end; e++)
        acc += g_hw3[__ldg(&g_csr_src[e])];
    OUT[node] = fmaxf(acc * g_dis[node] + b3[0], 0.f);
}

// ---------------- launch ---------------------------------------------------
extern "C" void kernel_launch(void* const* d_in, const int* in_sizes, int n_in,
                              void* d_out, int out_size) {
    const float* x  = (const float*)d_in[0];
    const int*   ei = (const int*)d_in[1];
    const float* W1 = (const float*)d_in[2];
    const float* b1 = (const float*)d_in[3];
    const float* W2 = (const float*)d_in[4];
    const float* b2 = (const float*)d_in[5];
    const float* W3 = (const float*)d_in[6];
    const float* b3 = (const float*)d_in[7];
    float* out = (float*)d_out;

    const int* src = ei;
    const int* dst = ei + N_EDGES;

    __half *hw, *acth;
    cudaGetSymbolAddress((void**)&hw,   g_hw);
    cudaGetSymbolAddress((void**)&acth, g_acth);
    int* counts; cudaGetSymbolAddress((void**)&counts, g_counts);

    static bool attr_set = false;
    if (!attr_set) {
        cudaFuncSetAttribute(gemm_1t<false>,
                             cudaFuncAttributeMaxDynamicSharedMemorySize, GEMM_SMEM);
        cudaFuncSetAttribute(gemm_1t<true>,
                             cudaFuncAttributeMaxDynamicSharedMemorySize, GEMM_SMEM);
        attr_set = true;
    }

    int nb_nodes = (N_NODES + 255) / 256;
    int nb_edge4 = (N_EDGES / 4 + 255) / 256;
    int nb_edge2 = (N_EDGES / 2 + 255) / 256;
    int nb_warp  = (N_NODES * 32 + 255) / 256;
    int nb_gemm  = (N_NODES + 127) / 128;

    // preprocessing: unordered CSR by dst (rank-based, atomic-free placement)
    cudaMemsetAsync(counts, 0, (N_NODES + 1) * sizeof(int));
    hist_kernel<<<nb_edge4, 256>>>(dst);
    prefix_kernel<<<nb_nodes, 256>>>();
    place_kernel<<<nb_edge2, 256>>>(src, dst);

    // layer 1 (A = x fp32, converted inline)
    gemm_1t<false><<<nb_gemm, 256, GEMM_SMEM>>>(x, nullptr, W1, hw, N_NODES);
    agg128_kernel<false><<<nb_warp, 256>>>(hw, b1, acth, nullptr);
    // layer 2 (A = act fp16 direct) + fused layer-3 GEMV
    gemm_1t<true><<<nb_gemm, 256, GEMM_SMEM>>>(nullptr, acth, W2, hw, N_NODES);
    agg128_kernel<true><<<nb_warp, 256>>>(hw, b2, nullptr, W3);
    // layer 3 aggregation
    agg3_kernel<<<nb_nodes, 256>>>(b3, out);
}